// round 1
// baseline (speedup 1.0000x reference)
#include <cuda_runtime.h>

// Hybrid_Conv2d: out[b] = conv2d(x[b], W_0 + cov[b]*W_1), 3x3, pad 1, stride 1
// B=32, CIN=COUT=64, H=W=128.
//
// Round 1: fp32 direct conv baseline.
//  - Each block: one batch b, 8 output channels, 16 output rows, all 128 cols.
//  - Per-block weights (8 co x 64 ci x 9) built once in SMEM from W0 + cov[b]*W1.
//  - Input staged in SMEM in chunks of 8 channels x 18 rows x 130 cols (halo).
//  - 512 threads: thread = (col 0..127, rowgroup 0..3); each thread accumulates
//    8 couts x 4 rows = 32 fp32 accumulators.

#define B_       32
#define C_       64
#define HW_      128
#define CO_T     8
#define RH       16
#define CI_T     8
#define PAD_H    18        // RH + 2 halo rows
#define PAD_W    130       // 128 + 2 halo cols
#define NTHREADS 512

#define SW_ELEMS  (CO_T * C_ * 9)          // 4608 floats  (18432 B)
#define SIN_ELEMS (CI_T * PAD_H * PAD_W)   // 18720 floats (74880 B)
#define SMEM_BYTES ((SW_ELEMS + SIN_ELEMS) * 4)   // 93312 B

extern __shared__ float smem_dyn[];

__global__ __launch_bounds__(NTHREADS, 1)
void hybrid_conv2d_kernel(const float* __restrict__ x,
                          const float* __restrict__ cov,
                          const float* __restrict__ W0,
                          const float* __restrict__ W1,
                          float* __restrict__ out) {
    float* sW  = smem_dyn;             // [CO_T][C_][9]
    float* sIn = smem_dyn + SW_ELEMS;  // [CI_T][PAD_H][PAD_W]

    const int b       = blockIdx.z;
    const int rowTile = blockIdx.y;
    const int coG     = blockIdx.x;
    const int tid     = threadIdx.x;
    const int xcol    = tid & 127;     // output column
    const int r0      = (tid >> 7) * 4; // first of 4 output rows (local)

    // ---- build per-batch weight slice: W0 + cov[b]*W1, 8 couts x 64 ci x 9 ----
    const float cv = cov[b];
    for (int i = tid; i < SW_ELEMS; i += NTHREADS) {
        int co  = i / (C_ * 9);
        int rem = i - co * (C_ * 9);
        int g   = ((coG * CO_T + co) * C_) * 9 + rem;
        sW[i] = W0[g] + cv * W1[g];
    }

    float acc[CO_T][4];
    #pragma unroll
    for (int co = 0; co < CO_T; co++)
        #pragma unroll
        for (int r = 0; r < 4; r++)
            acc[co][r] = 0.0f;

    const int y0 = rowTile * RH;

    for (int ci0 = 0; ci0 < C_; ci0 += CI_T) {
        __syncthreads();  // prev compute done (and, on iter 0, weight build done)

        // ---- stage input chunk: CI_T channels x PAD_H rows x PAD_W cols ----
        for (int e = tid; e < SIN_ELEMS; e += NTHREADS) {
            int ci  = e / (PAD_H * PAD_W);
            int rem = e - ci * (PAD_H * PAD_W);
            int row = rem / PAD_W;
            int col = rem - row * PAD_W;
            int gy  = y0 + row - 1;
            int gx  = col - 1;
            float v = 0.0f;
            if ((unsigned)gy < HW_ && (unsigned)gx < HW_)
                v = x[((b * C_ + ci0 + ci) * HW_ + gy) * HW_ + gx];
            sIn[e] = v;
        }
        __syncthreads();

        // ---- compute ----
        #pragma unroll
        for (int ci = 0; ci < CI_T; ci++) {
            // 6 input rows x 3 cols cover 4 output rows of a 3x3 window
            float in[6][3];
            #pragma unroll
            for (int rr = 0; rr < 6; rr++)
                #pragma unroll
                for (int cc = 0; cc < 3; cc++)
                    in[rr][cc] = sIn[(ci * PAD_H + r0 + rr) * PAD_W + xcol + cc];

            #pragma unroll
            for (int co = 0; co < CO_T; co++) {
                const float* wp = &sW[(co * C_ + ci0 + ci) * 9];
                float w[9];
                #pragma unroll
                for (int k = 0; k < 9; k++) w[k] = wp[k];

                #pragma unroll
                for (int r = 0; r < 4; r++)
                    #pragma unroll
                    for (int ky = 0; ky < 3; ky++)
                        #pragma unroll
                        for (int kx = 0; kx < 3; kx++)
                            acc[co][r] = fmaf(w[ky * 3 + kx], in[r + ky][kx], acc[co][r]);
            }
        }
    }

    // ---- store ----
    #pragma unroll
    for (int co = 0; co < CO_T; co++) {
        const int cog = coG * CO_T + co;
        #pragma unroll
        for (int r = 0; r < 4; r++) {
            const int y = y0 + r0 + r;
            out[((b * C_ + cog) * HW_ + y) * HW_ + xcol] = acc[co][r];
        }
    }
}

extern "C" void kernel_launch(void* const* d_in, const int* in_sizes, int n_in,
                              void* d_out, int out_size) {
    (void)in_sizes; (void)n_in; (void)out_size;
    const float* x   = (const float*)d_in[0];
    const float* cov = (const float*)d_in[1];
    const float* W0  = (const float*)d_in[2];
    const float* W1  = (const float*)d_in[3];
    float* out = (float*)d_out;

    cudaFuncSetAttribute(hybrid_conv2d_kernel,
                         cudaFuncAttributeMaxDynamicSharedMemorySize, SMEM_BYTES);

    dim3 grid(C_ / CO_T, HW_ / RH, B_);  // (8 cout groups, 8 row tiles, 32 batches)
    hybrid_conv2d_kernel<<<grid, NTHREADS, SMEM_BYTES>>>(x, cov, W0, W1, out);
}